// round 15
// baseline (speedup 1.0000x reference)
#include <cuda_runtime.h>
#include <cuda_bf16.h>
#include <cstdint>

#define NN 50000
#define NE 800000
#define IN_CH 512
#define HID 256
#define OUTC 128
#define NSCAN_BLK 196                        // 196*256 = 50176 >= NN

// ---- scratch (static device globals; no allocations allowed) ----
__device__ float g_dinv[NN];
__device__ int   g_cnt[NN];
__device__ int   g_rowptr[NN + 1];
__device__ int   g_cursor[NN];
__device__ int   g_esrc[NE];
__device__ int   g_bsum[256];
__device__ int   g_boff[256];
__device__ float g_h1[(size_t)NN * HID];
__device__ float g_h2[(size_t)NN * OUTC];

__device__ __nv_bfloat16 g_xhi[(size_t)NN * IN_CH];
__device__ __nv_bfloat16 g_xlo[(size_t)NN * IN_CH];
__device__ __nv_bfloat16 g_aghi[(size_t)NN * HID];
__device__ __nv_bfloat16 g_aglo[(size_t)NN * HID];
__device__ __nv_bfloat16 g_w1hi[HID * IN_CH];     // transposed [N][K]
__device__ __nv_bfloat16 g_w1lo[HID * IN_CH];
__device__ __nv_bfloat16 g_w2hi[OUTC * HID];
__device__ __nv_bfloat16 g_w2lo[OUTC * HID];

// ============================ helpers ============================
__device__ __forceinline__ uint32_t smem_u32(const void* p) {
    uint32_t a;
    asm("{ .reg .u64 t; cvta.to.shared.u64 t, %1; cvt.u32.u64 %0, t; }" : "=r"(a) : "l"(p));
    return a;
}
__device__ __forceinline__ void ldmx4(uint32_t* r, uint32_t addr) {
    asm volatile("ldmatrix.sync.aligned.m8n8.x4.shared.b16 {%0,%1,%2,%3}, [%4];"
        : "=r"(r[0]), "=r"(r[1]), "=r"(r[2]), "=r"(r[3]) : "r"(addr));
}
__device__ __forceinline__ void mma16816(float* c, const uint32_t* a,
                                         uint32_t b0, uint32_t b1) {
    asm volatile("mma.sync.aligned.m16n8k16.row.col.f32.bf16.bf16.f32 "
        "{%0,%1,%2,%3}, {%4,%5,%6,%7}, {%8,%9}, {%0,%1,%2,%3};"
        : "+f"(c[0]), "+f"(c[1]), "+f"(c[2]), "+f"(c[3])
        : "r"(a[0]), "r"(a[1]), "r"(a[2]), "r"(a[3]), "r"(b0), "r"(b1));
}

// per-block dtype detection: int64 ids (< 2^31) -> all odd 32-bit words zero.
__device__ __forceinline__ int detect_is64(const unsigned int* __restrict__ w) {
    __shared__ unsigned sacc[8];
    unsigned acc = 0;
    for (int i = threadIdx.x; i < 2048; i += blockDim.x) acc |= w[2 * i + 1];
#pragma unroll
    for (int o = 16; o; o >>= 1) acc |= __shfl_xor_sync(0xFFFFFFFFu, acc, o);
    if ((threadIdx.x & 31) == 0) sacc[threadIdx.x >> 5] = acc;
    __syncthreads();
    unsigned tot = 0;
#pragma unroll
    for (int i = 0; i < 8; i++) tot |= sacc[i];
    return tot == 0;
}
__device__ __forceinline__ int edge_idx(const void* ei, size_t pos, int is64) {
    int i = is64 ? (int)((const long long*)ei)[pos] : ((const int*)ei)[pos];
    return i < 0 ? 0 : (i >= NN ? NN - 1 : i);   // clamp: trap insurance
}

// block-wide inclusive scan of one int per thread (256 threads)
__device__ __forceinline__ int block_incl_scan(int v) {
    __shared__ int ws[8];
    int lane = threadIdx.x & 31, w = threadIdx.x >> 5;
    int x = v;
#pragma unroll
    for (int o = 1; o < 32; o <<= 1) {
        int y = __shfl_up_sync(0xFFFFFFFFu, x, o);
        if (lane >= o) x += y;
    }
    if (lane == 31) ws[w] = x;
    __syncthreads();
    if (w == 0) {
        int y = (lane < 8) ? ws[lane] : 0;
#pragma unroll
        for (int o = 1; o < 8; o <<= 1) {
            int z = __shfl_up_sync(0xFFFFFFFFu, y, o);
            if (lane >= o) y += z;
        }
        if (lane < 8) ws[lane] = y;
    }
    __syncthreads();
    return x + (w ? ws[w - 1] : 0);
}

// ============================ CSR build ============================
__global__ void k_prep() {
    int i = blockIdx.x * blockDim.x + threadIdx.x;
    if (i < NN) g_cnt[i] = 0;
}
__global__ void k_count(const void* __restrict__ ei) {
    int is64 = detect_is64((const unsigned int*)ei);
    int e = blockIdx.x * blockDim.x + threadIdx.x;
    if (e < NE) atomicAdd(&g_cnt[edge_idx(ei, (size_t)NE + e, is64)], 1);
}
__global__ void k_scan1() {
    int i = blockIdx.x * 256 + threadIdx.x;
    int v = (i < NN) ? g_cnt[i] : 0;
    int incl = block_incl_scan(v);
    if (i < NN) g_rowptr[i] = incl - v;
    if (threadIdx.x == 255) g_bsum[blockIdx.x] = incl;
}
__global__ void k_scan2() {
    int b = threadIdx.x;
    int v = (b < NSCAN_BLK) ? g_bsum[b] : 0;
    int incl = block_incl_scan(v);
    if (b < NSCAN_BLK) g_boff[b] = incl - v;
    if (b == 255) g_rowptr[NN] = incl;
}
__global__ void k_scan3() {
    int i = blockIdx.x * 256 + threadIdx.x;
    if (i >= NN) return;
    int r = g_rowptr[i] + g_boff[blockIdx.x];
    g_rowptr[i] = r;
    g_cursor[i] = r;
    g_dinv[i]   = rsqrtf((float)g_cnt[i] + 1.0f);
}
__global__ void k_fill(const void* __restrict__ ei) {
    int is64 = detect_is64((const unsigned int*)ei);
    int e = blockIdx.x * blockDim.x + threadIdx.x;
    if (e >= NE) return;
    int s = edge_idx(ei, (size_t)e, is64);
    int d = edge_idx(ei, (size_t)NE + e, is64);
    g_esrc[atomicAdd(&g_cursor[d], 1)] = s;
}

// ============================ splits ============================
__global__ void k_splitT(const float* __restrict__ W, __nv_bfloat16* __restrict__ hi,
                         __nv_bfloat16* __restrict__ lo, int K, int N) {
    int idx = blockIdx.x * blockDim.x + threadIdx.x;
    if (idx >= K * N) return;
    int k = idx / N, n = idx - k * N;
    float v = W[idx];
    __nv_bfloat16 h = __float2bfloat16(v);
    hi[(size_t)n * K + k] = h;
    lo[(size_t)n * K + k] = __float2bfloat16(v - __bfloat162float(h));
}

__global__ void k_splitX(const float* __restrict__ in, __nv_bfloat16* __restrict__ hi,
                         __nv_bfloat16* __restrict__ lo, int n4) {
    int i = blockIdx.x * blockDim.x + threadIdx.x;
    if (i >= n4) return;
    float4 v = ((const float4*)in)[i];
    __nv_bfloat16 hx = __float2bfloat16(v.x), hy = __float2bfloat16(v.y);
    __nv_bfloat16 hz = __float2bfloat16(v.z), hw = __float2bfloat16(v.w);
    ((__nv_bfloat162*)hi)[2 * i]     = __nv_bfloat162{hx, hy};
    ((__nv_bfloat162*)hi)[2 * i + 1] = __nv_bfloat162{hz, hw};
    ((__nv_bfloat162*)lo)[2 * i] = __nv_bfloat162{
        __float2bfloat16(v.x - __bfloat162float(hx)),
        __float2bfloat16(v.y - __bfloat162float(hy))};
    ((__nv_bfloat162*)lo)[2 * i + 1] = __nv_bfloat162{
        __float2bfloat16(v.z - __bfloat162float(hz)),
        __float2bfloat16(v.w - __bfloat162float(hw))};
}

// ============================ HMMA GEMM (bf16 hi/lo, cp.async 2-stage) ========
// C[M,NT] = A[M,K] @ Bt[NT,K]^T.  CTA 128x128, 8 warps (2m x 4n), BK=32.
// cp.async.cg loads (no prefetch registers) -> 2 CTAs/SM.
template <int K, int NT>
__global__ __launch_bounds__(256, 2)
void k_mma(const __nv_bfloat16* __restrict__ Ahi, const __nv_bfloat16* __restrict__ Alo,
           const __nv_bfloat16* __restrict__ Bhi, const __nv_bfloat16* __restrict__ Blo,
           float* __restrict__ C) {
    constexpr int ST = 40;
    constexpr int BUF = 128 * ST;                 // elements per tile buffer
    constexpr int CHUNKS = K / 32;
    extern __shared__ __align__(16) char smraw[];
    __nv_bfloat16* s = (__nv_bfloat16*)smraw;     // [2 stages][4 bufs][BUF]

    const int tid  = threadIdx.x;
    const int lane = tid & 31;
    const int wid  = tid >> 5;
    const int wm   = (wid & 1) * 64;
    const int wn   = (wid >> 1) * 32;
    const int m0   = blockIdx.x * 128;
    const int n0   = blockIdx.y * 128;

    float acc[4][4][4];
#pragma unroll
    for (int mt = 0; mt < 4; mt++)
#pragma unroll
        for (int nt = 0; nt < 4; nt++)
#pragma unroll
            for (int j = 0; j < 4; j++) acc[mt][nt][j] = 0.0f;

    const int a_row = wm + (lane & 15);
    const int a_kof = ((lane >> 4) & 1) << 3;
    const int b_row = wn + (lane & 7) + (((lane >> 4) & 1) << 3);
    const int b_kof = ((lane >> 3) & 1) << 3;

    // async-load one K-chunk (4 tiles of 128 rows x 32 bf16) into stage ch&1
    auto issue_chunk = [&](int ch) {
        const int kc0 = ch * 32;
        const int st  = ch & 1;
#pragma unroll
        for (int it = 0; it < 8; it++) {
            int j   = it * 256 + tid;             // 0..2047
            int buf = j >> 9;                     // 0..3
            int r   = (j >> 2) & 127;
            int c   = j & 3;                      // 16B chunk within row
            const __nv_bfloat16* gb =
                (buf == 0) ? Ahi : (buf == 1) ? Alo : (buf == 2) ? Bhi : Blo;
            int grow = (buf < 2) ? (m0 + r) : (n0 + r);
            int sz = 16;
            if (buf < 2 && grow >= NN) { grow = NN - 1; sz = 0; }   // zero-fill
            uint32_t dst = smem_u32(s + (st * 4 + buf) * BUF + r * ST + c * 8);
            const void* src = gb + (size_t)grow * K + kc0 + c * 8;
            asm volatile("cp.async.cg.shared.global [%0], [%1], 16, %2;"
                         :: "r"(dst), "l"(src), "r"(sz));
        }
        asm volatile("cp.async.commit_group;" ::: "memory");
    };

    issue_chunk(0);
    if (CHUNKS > 1) issue_chunk(1);

    for (int ch = 0; ch < CHUNKS; ch++) {
        if (ch + 1 < CHUNKS)
            asm volatile("cp.async.wait_group 1;" ::: "memory");
        else
            asm volatile("cp.async.wait_group 0;" ::: "memory");
        __syncthreads();

        const int st = ch & 1;
        uint32_t base0 = smem_u32(s + (st * 4 + 0) * BUF);
        uint32_t base1 = smem_u32(s + (st * 4 + 1) * BUF);
        uint32_t base2 = smem_u32(s + (st * 4 + 2) * BUF);
        uint32_t base3 = smem_u32(s + (st * 4 + 3) * BUF);
#pragma unroll
        for (int ks = 0; ks < 2; ks++) {
            uint32_t ah[4][4], al[4][4], bh[2][4], bl[2][4];
#pragma unroll
            for (int mt = 0; mt < 4; mt++) {
                uint32_t off = ((a_row + mt * 16) * ST + ks * 16 + a_kof) * 2;
                ldmx4(ah[mt], base0 + off);
                ldmx4(al[mt], base1 + off);
            }
#pragma unroll
            for (int p = 0; p < 2; p++) {
                uint32_t off = ((b_row + p * 16) * ST + ks * 16 + b_kof) * 2;
                ldmx4(bh[p], base2 + off);
                ldmx4(bl[p], base3 + off);
            }
#pragma unroll
            for (int mt = 0; mt < 4; mt++)
#pragma unroll
                for (int nt = 0; nt < 4; nt++) {
                    int p = nt >> 1, q = (nt & 1) * 2;
                    mma16816(acc[mt][nt], ah[mt], bh[p][q], bh[p][q + 1]);
                    mma16816(acc[mt][nt], ah[mt], bl[p][q], bl[p][q + 1]);
                    mma16816(acc[mt][nt], al[mt], bh[p][q], bh[p][q + 1]);
                }
        }
        __syncthreads();                          // stage st fully consumed
        if (ch + 2 < CHUNKS) issue_chunk(ch + 2); // refill stage st (async)
    }

    // ---- epilogue ----
#pragma unroll
    for (int mt = 0; mt < 4; mt++) {
        int row0 = m0 + wm + mt * 16 + (lane >> 2);
        int row1 = row0 + 8;
#pragma unroll
        for (int nt = 0; nt < 4; nt++) {
            int col = n0 + wn + nt * 8 + (lane & 3) * 2;
            if (row0 < NN)
                *(float2*)(C + (size_t)row0 * NT + col) =
                    make_float2(acc[mt][nt][0], acc[mt][nt][1]);
            if (row1 < NN)
                *(float2*)(C + (size_t)row1 * NT + col) =
                    make_float2(acc[mt][nt][2], acc[mt][nt][3]);
        }
    }
}

// ============================ fused CSR gather ============================
template <int C, bool SPLIT>
__global__ __launch_bounds__(256)
void k_gather(const float* __restrict__ h, const float* __restrict__ bias,
              float* __restrict__ outf, __nv_bfloat16* __restrict__ outhi,
              __nv_bfloat16* __restrict__ outlo) {
    constexpr int L = C / 4;
    constexpr int NPB = 256 / L;
    int node = blockIdx.x * NPB + threadIdx.x / L;
    if (node >= NN) return;
    int lane = threadIdx.x % L;

    const float4* h4 = (const float4*)h;
    float dd = g_dinv[node];
    float4 self = h4[(size_t)node * L + lane];
    float ws = dd * dd;
    float4 acc = make_float4(self.x * ws, self.y * ws, self.z * ws, self.w * ws);

    int e   = g_rowptr[node];
    int end = g_rowptr[node + 1];
    for (; e + 1 < end; e += 2) {
        int s0 = __ldg(&g_esrc[e]);
        int s1 = __ldg(&g_esrc[e + 1]);
        float w0 = __ldg(&g_dinv[s0]) * dd;
        float w1 = __ldg(&g_dinv[s1]) * dd;
        float4 v0 = h4[(size_t)s0 * L + lane];
        float4 v1 = h4[(size_t)s1 * L + lane];
        acc.x = fmaf(v0.x, w0, fmaf(v1.x, w1, acc.x));
        acc.y = fmaf(v0.y, w0, fmaf(v1.y, w1, acc.y));
        acc.z = fmaf(v0.z, w0, fmaf(v1.z, w1, acc.z));
        acc.w = fmaf(v0.w, w0, fmaf(v1.w, w1, acc.w));
    }
    if (e < end) {
        int s0 = __ldg(&g_esrc[e]);
        float w0 = __ldg(&g_dinv[s0]) * dd;
        float4 v0 = h4[(size_t)s0 * L + lane];
        acc.x = fmaf(v0.x, w0, acc.x);
        acc.y = fmaf(v0.y, w0, acc.y);
        acc.z = fmaf(v0.z, w0, acc.z);
        acc.w = fmaf(v0.w, w0, acc.w);
    }

    float4 b = ((const float4*)bias)[lane];
    acc.x += b.x; acc.y += b.y; acc.z += b.z; acc.w += b.w;

    if (SPLIT) {
        acc.x = fmaxf(acc.x, 0.f); acc.y = fmaxf(acc.y, 0.f);
        acc.z = fmaxf(acc.z, 0.f); acc.w = fmaxf(acc.w, 0.f);
        __nv_bfloat16 hx = __float2bfloat16(acc.x), hy = __float2bfloat16(acc.y);
        __nv_bfloat16 hz = __float2bfloat16(acc.z), hw = __float2bfloat16(acc.w);
        size_t p2 = ((size_t)node * L + lane) * 2;
        ((__nv_bfloat162*)outhi)[p2]     = __nv_bfloat162{hx, hy};
        ((__nv_bfloat162*)outhi)[p2 + 1] = __nv_bfloat162{hz, hw};
        ((__nv_bfloat162*)outlo)[p2] = __nv_bfloat162{
            __float2bfloat16(acc.x - __bfloat162float(hx)),
            __float2bfloat16(acc.y - __bfloat162float(hy))};
        ((__nv_bfloat162*)outlo)[p2 + 1] = __nv_bfloat162{
            __float2bfloat16(acc.z - __bfloat162float(hz)),
            __float2bfloat16(acc.w - __bfloat162float(hw))};
    } else {
        ((float4*)outf)[(size_t)node * L + lane] = acc;
    }
}

// ============================ launch ============================
extern "C" void kernel_launch(void* const* d_in, const int* in_sizes, int n_in,
                              void* d_out, int out_size) {
    const float* x  = (const float*)d_in[0];
    const void*  ei = d_in[1];
    const float* W1 = (const float*)d_in[2];
    const float* b1 = (const float*)d_in[3];
    const float* W2 = (const float*)d_in[4];
    const float* b2 = (const float*)d_in[5];
    float*       out = (float*)d_out;

    float *h1, *h2;
    __nv_bfloat16 *xhi, *xlo, *aghi, *aglo, *w1hi, *w1lo, *w2hi, *w2lo;
    cudaGetSymbolAddress((void**)&h1, g_h1);
    cudaGetSymbolAddress((void**)&h2, g_h2);
    cudaGetSymbolAddress((void**)&xhi, g_xhi);
    cudaGetSymbolAddress((void**)&xlo, g_xlo);
    cudaGetSymbolAddress((void**)&aghi, g_aghi);
    cudaGetSymbolAddress((void**)&aglo, g_aglo);
    cudaGetSymbolAddress((void**)&w1hi, g_w1hi);
    cudaGetSymbolAddress((void**)&w1lo, g_w1lo);
    cudaGetSymbolAddress((void**)&w2hi, g_w2hi);
    cudaGetSymbolAddress((void**)&w2lo, g_w2lo);

    // one-time host-object setup (no device memory involved)
    static cudaStream_t s2 = nullptr;
    static cudaEvent_t ev_fork = nullptr, ev_join = nullptr;
    if (!s2) {
        cudaStreamCreateWithFlags(&s2, cudaStreamNonBlocking);
        cudaEventCreateWithFlags(&ev_fork, cudaEventDisableTiming);
        cudaEventCreateWithFlags(&ev_join, cudaEventDisableTiming);
        constexpr int SMEM = 2 * 4 * 128 * 40 * 2;   // 81920 B
        cudaFuncSetAttribute(k_mma<IN_CH, HID>,
                             cudaFuncAttributeMaxDynamicSharedMemorySize, SMEM);
        cudaFuncSetAttribute(k_mma<HID, OUTC>,
                             cudaFuncAttributeMaxDynamicSharedMemorySize, SMEM);
    }
    constexpr int SMEM = 2 * 4 * 128 * 40 * 2;       // 81920 B

    const int NB = (NN + 127) / 128;   // 391

    // ---- fork ----
    cudaEventRecord(ev_fork, 0);
    cudaStreamWaitEvent(s2, ev_fork, 0);

    // side stream: splitT2 + CSR build (hidden under splitX + GEMM1)
    k_splitT<<<(HID * OUTC + 255) / 256, 256, 0, s2>>>(W2, w2hi, w2lo, HID, OUTC);
    k_prep  <<<(NN + 255) / 256, 256, 0, s2>>>();
    k_count <<<(NE + 255) / 256, 256, 0, s2>>>(ei);
    k_scan1 <<<NSCAN_BLK, 256, 0, s2>>>();
    k_scan2 <<<1, 256, 0, s2>>>();
    k_scan3 <<<NSCAN_BLK, 256, 0, s2>>>();
    k_fill  <<<(NE + 255) / 256, 256, 0, s2>>>(ei);
    cudaEventRecord(ev_join, s2);

    // main stream: splits + GEMM1 (bf16 operands, cp.async pipeline)
    k_splitT<<<(IN_CH * HID + 255) / 256, 256>>>(W1, w1hi, w1lo, IN_CH, HID);
    k_splitX<<<(NN * IN_CH / 4 + 255) / 256, 256>>>(x, xhi, xlo, NN * IN_CH / 4);
    dim3 g1(NB, HID / 128);
    k_mma<IN_CH, HID><<<g1, 256, SMEM>>>(xhi, xlo, w1hi, w1lo, h1);

    // ---- join, then serial tail (proven R14 shape) ----
    cudaStreamWaitEvent(0, ev_join, 0);
    k_gather<HID, true><<<(NN + 3) / 4, 256>>>(h1, b1, nullptr, aghi, aglo);

    dim3 g2(NB, OUTC / 128);
    k_mma<HID, OUTC><<<g2, 256, SMEM>>>(nullptr != aghi ? aghi : aghi, aglo, w2hi, w2lo, h2);
    k_gather<OUTC, false><<<(NN + 7) / 8, 256>>>(h2, b2, out, nullptr, nullptr);
}

// round 16
// speedup vs baseline: 1.0400x; 1.0400x over previous
#include <cuda_runtime.h>
#include <cuda_bf16.h>
#include <cstdint>

#define NN 50000
#define NE 800000
#define IN_CH 512
#define HID 256
#define OUTC 128
#define NSCAN_BLK 196                        // 196*256 = 50176 >= NN

// ---- scratch (static device globals; no allocations allowed) ----
__device__ float g_dinv[NN];
__device__ int   g_cnt[NN];
__device__ int   g_rowptr[NN + 1];
__device__ int   g_cursor[NN];
__device__ int   g_esrc[NE];
__device__ int   g_bsum[256];
__device__ int   g_boff[256];
__device__ float g_h1[(size_t)NN * HID];
__device__ float g_h2[(size_t)NN * OUTC];

__device__ __nv_bfloat16 g_aghi[(size_t)NN * HID];
__device__ __nv_bfloat16 g_aglo[(size_t)NN * HID];
__device__ __nv_bfloat16 g_w1hi[HID * IN_CH];     // transposed [N][K]
__device__ __nv_bfloat16 g_w1lo[HID * IN_CH];
__device__ __nv_bfloat16 g_w2hi[OUTC * HID];
__device__ __nv_bfloat16 g_w2lo[OUTC * HID];

// ============================ helpers ============================
__device__ __forceinline__ uint32_t smem_u32(const void* p) {
    uint32_t a;
    asm("{ .reg .u64 t; cvta.to.shared.u64 t, %1; cvt.u32.u64 %0, t; }" : "=r"(a) : "l"(p));
    return a;
}
__device__ __forceinline__ void ldmx4(uint32_t* r, uint32_t addr) {
    asm volatile("ldmatrix.sync.aligned.m8n8.x4.shared.b16 {%0,%1,%2,%3}, [%4];"
        : "=r"(r[0]), "=r"(r[1]), "=r"(r[2]), "=r"(r[3]) : "r"(addr));
}
__device__ __forceinline__ void mma16816(float* c, const uint32_t* a,
                                         uint32_t b0, uint32_t b1) {
    asm volatile("mma.sync.aligned.m16n8k16.row.col.f32.bf16.bf16.f32 "
        "{%0,%1,%2,%3}, {%4,%5,%6,%7}, {%8,%9}, {%0,%1,%2,%3};"
        : "+f"(c[0]), "+f"(c[1]), "+f"(c[2]), "+f"(c[3])
        : "r"(a[0]), "r"(a[1]), "r"(a[2]), "r"(a[3]), "r"(b0), "r"(b1));
}

// per-block dtype detection: int64 ids (< 2^31) -> all odd 32-bit words zero.
__device__ __forceinline__ int detect_is64(const unsigned int* __restrict__ w) {
    __shared__ unsigned sacc[8];
    unsigned acc = 0;
    for (int i = threadIdx.x; i < 2048; i += blockDim.x) acc |= w[2 * i + 1];
#pragma unroll
    for (int o = 16; o; o >>= 1) acc |= __shfl_xor_sync(0xFFFFFFFFu, acc, o);
    if ((threadIdx.x & 31) == 0) sacc[threadIdx.x >> 5] = acc;
    __syncthreads();
    unsigned tot = 0;
#pragma unroll
    for (int i = 0; i < 8; i++) tot |= sacc[i];
    return tot == 0;
}
__device__ __forceinline__ int edge_idx(const void* ei, size_t pos, int is64) {
    int i = is64 ? (int)((const long long*)ei)[pos] : ((const int*)ei)[pos];
    return i < 0 ? 0 : (i >= NN ? NN - 1 : i);   // clamp: trap insurance
}

// block-wide inclusive scan of one int per thread (256 threads)
__device__ __forceinline__ int block_incl_scan(int v) {
    __shared__ int ws[8];
    int lane = threadIdx.x & 31, w = threadIdx.x >> 5;
    int x = v;
#pragma unroll
    for (int o = 1; o < 32; o <<= 1) {
        int y = __shfl_up_sync(0xFFFFFFFFu, x, o);
        if (lane >= o) x += y;
    }
    if (lane == 31) ws[w] = x;
    __syncthreads();
    if (w == 0) {
        int y = (lane < 8) ? ws[lane] : 0;
#pragma unroll
        for (int o = 1; o < 8; o <<= 1) {
            int z = __shfl_up_sync(0xFFFFFFFFu, y, o);
            if (lane >= o) y += z;
        }
        if (lane < 8) ws[lane] = y;
    }
    __syncthreads();
    return x + (w ? ws[w - 1] : 0);
}

// ============================ CSR build ============================
__global__ void k_prep() {
    int i = blockIdx.x * blockDim.x + threadIdx.x;
    if (i < NN) g_cnt[i] = 0;
}
__global__ void k_count(const void* __restrict__ ei) {
    int is64 = detect_is64((const unsigned int*)ei);
    int e = blockIdx.x * blockDim.x + threadIdx.x;
    if (e < NE) atomicAdd(&g_cnt[edge_idx(ei, (size_t)NE + e, is64)], 1);
}
__global__ void k_scan1() {
    int i = blockIdx.x * 256 + threadIdx.x;
    int v = (i < NN) ? g_cnt[i] : 0;
    int incl = block_incl_scan(v);
    if (i < NN) g_rowptr[i] = incl - v;
    if (threadIdx.x == 255) g_bsum[blockIdx.x] = incl;
}
__global__ void k_scan2() {
    int b = threadIdx.x;
    int v = (b < NSCAN_BLK) ? g_bsum[b] : 0;
    int incl = block_incl_scan(v);
    if (b < NSCAN_BLK) g_boff[b] = incl - v;
    if (b == 255) g_rowptr[NN] = incl;
}
__global__ void k_scan3() {
    int i = blockIdx.x * 256 + threadIdx.x;
    if (i >= NN) return;
    int r = g_rowptr[i] + g_boff[blockIdx.x];
    g_rowptr[i] = r;
    g_cursor[i] = r;
    g_dinv[i]   = rsqrtf((float)g_cnt[i] + 1.0f);
}
__global__ void k_fill(const void* __restrict__ ei) {
    int is64 = detect_is64((const unsigned int*)ei);
    int e = blockIdx.x * blockDim.x + threadIdx.x;
    if (e >= NE) return;
    int s = edge_idx(ei, (size_t)e, is64);
    int d = edge_idx(ei, (size_t)NE + e, is64);
    g_esrc[atomicAdd(&g_cursor[d], 1)] = s;
}

// ============================ weight split (transposed) ============================
__global__ void k_splitT(const float* __restrict__ W, __nv_bfloat16* __restrict__ hi,
                         __nv_bfloat16* __restrict__ lo, int K, int N) {
    int idx = blockIdx.x * blockDim.x + threadIdx.x;
    if (idx >= K * N) return;
    int k = idx / N, n = idx - k * N;
    float v = W[idx];
    __nv_bfloat16 h = __float2bfloat16(v);
    hi[(size_t)n * K + k] = h;
    lo[(size_t)n * K + k] = __float2bfloat16(v - __bfloat162float(h));
}

// ============================ GEMM1: fused-AFP32 register-prefetch (R14) ======
// C[M,NT] = A32[M,K] @ Bt[NT,K]^T, A split to bf16 hi/lo at smem-store time.
template <int K, int NT>
__global__ __launch_bounds__(256)
void k_mma_f32(const float* __restrict__ A32,
               const __nv_bfloat16* __restrict__ Bhi, const __nv_bfloat16* __restrict__ Blo,
               float* __restrict__ C) {
    constexpr int ST = 40;
    constexpr int CHUNKS = K / 32;
    __shared__ __align__(16) __nv_bfloat16 s[4][128 * ST];  // Ahi, Alo, Bhi, Blo

    const int tid  = threadIdx.x;
    const int lane = tid & 31;
    const int wid  = tid >> 5;
    const int wm   = (wid & 1) * 64;
    const int wn   = (wid >> 1) * 32;
    const int m0   = blockIdx.x * 128;
    const int n0   = blockIdx.y * 128;

    float acc[4][4][4];
#pragma unroll
    for (int mt = 0; mt < 4; mt++)
#pragma unroll
        for (int nt = 0; nt < 4; nt++)
#pragma unroll
            for (int j = 0; j < 4; j++) acc[mt][nt][j] = 0.0f;

    const int a_row = wm + (lane & 15);
    const int a_kof = ((lane >> 4) & 1) << 3;
    const int b_row = wn + (lane & 7) + (((lane >> 4) & 1) << 3);
    const int b_kof = ((lane >> 3) & 1) << 3;

    float4 pa[4], pb[4];

    auto load_chunk = [&](int kc0) {
#pragma unroll
        for (int it = 0; it < 4; it++) {
            int idx = it * 256 + tid;
            int r = idx >> 3, c = idx & 7;
            int row = m0 + r;
            pa[it] = (row < NN)
                ? ((const float4*)(A32 + (size_t)row * K + kc0))[c]
                : make_float4(0.f, 0.f, 0.f, 0.f);
        }
#pragma unroll
        for (int it = 0; it < 2; it++) {
            int idx = it * 256 + tid;
            int r = idx >> 2, c = idx & 3;
            int row = n0 + r;
            pb[it]     = ((const float4*)(Bhi + (size_t)row * K + kc0))[c];
            pb[2 + it] = ((const float4*)(Blo + (size_t)row * K + kc0))[c];
        }
    };

    auto store_chunk = [&]() {
#pragma unroll
        for (int it = 0; it < 4; it++) {
            int idx = it * 256 + tid;
            int r = idx >> 3, c = idx & 7;
            float4 v = pa[it];
            __nv_bfloat16 hx = __float2bfloat16(v.x), hy = __float2bfloat16(v.y);
            __nv_bfloat16 hz = __float2bfloat16(v.z), hw = __float2bfloat16(v.w);
            __nv_bfloat16* ph = &s[0][r * ST + c * 4];
            __nv_bfloat16* pl = &s[1][r * ST + c * 4];
            *(__nv_bfloat162*)(ph)     = __nv_bfloat162{hx, hy};
            *(__nv_bfloat162*)(ph + 2) = __nv_bfloat162{hz, hw};
            *(__nv_bfloat162*)(pl) = __nv_bfloat162{
                __float2bfloat16(v.x - __bfloat162float(hx)),
                __float2bfloat16(v.y - __bfloat162float(hy))};
            *(__nv_bfloat162*)(pl + 2) = __nv_bfloat162{
                __float2bfloat16(v.z - __bfloat162float(hz)),
                __float2bfloat16(v.w - __bfloat162float(hw))};
        }
#pragma unroll
        for (int it = 0; it < 2; it++) {
            int idx = it * 256 + tid;
            int r = idx >> 2, c = idx & 3;
            *(float4*)&s[2][r * ST + c * 8] = pb[it];
            *(float4*)&s[3][r * ST + c * 8] = pb[2 + it];
        }
    };

    load_chunk(0);
    for (int ch = 0; ch < CHUNKS; ch++) {
        store_chunk();
        __syncthreads();
        if (ch + 1 < CHUNKS) load_chunk((ch + 1) * 32);

#pragma unroll
        for (int ks = 0; ks < 2; ks++) {
            uint32_t ah[4][4], al[4][4], bh[2][4], bl[2][4];
#pragma unroll
            for (int mt = 0; mt < 4; mt++) {
                uint32_t off = ((a_row + mt * 16) * ST + ks * 16 + a_kof) * 2;
                ldmx4(ah[mt], smem_u32(&s[0][0]) + off);
                ldmx4(al[mt], smem_u32(&s[1][0]) + off);
            }
#pragma unroll
            for (int p = 0; p < 2; p++) {
                uint32_t off = ((b_row + p * 16) * ST + ks * 16 + b_kof) * 2;
                ldmx4(bh[p], smem_u32(&s[2][0]) + off);
                ldmx4(bl[p], smem_u32(&s[3][0]) + off);
            }
#pragma unroll
            for (int mt = 0; mt < 4; mt++)
#pragma unroll
                for (int nt = 0; nt < 4; nt++) {
                    int p = nt >> 1, q = (nt & 1) * 2;
                    mma16816(acc[mt][nt], ah[mt], bh[p][q], bh[p][q + 1]);
                    mma16816(acc[mt][nt], ah[mt], bl[p][q], bl[p][q + 1]);
                    mma16816(acc[mt][nt], al[mt], bh[p][q], bh[p][q + 1]);
                }
        }
        __syncthreads();
    }

#pragma unroll
    for (int mt = 0; mt < 4; mt++) {
        int row0 = m0 + wm + mt * 16 + (lane >> 2);
        int row1 = row0 + 8;
#pragma unroll
        for (int nt = 0; nt < 4; nt++) {
            int col = n0 + wn + nt * 8 + (lane & 3) * 2;
            if (row0 < NN)
                *(float2*)(C + (size_t)row0 * NT + col) =
                    make_float2(acc[mt][nt][0], acc[mt][nt][1]);
            if (row1 < NN)
                *(float2*)(C + (size_t)row1 * NT + col) =
                    make_float2(acc[mt][nt][2], acc[mt][nt][3]);
        }
    }
}

// ============================ GEMM2: bf16 cp.async 2-stage (R15) ==============
template <int K, int NT>
__global__ __launch_bounds__(256, 2)
void k_mma_bf(const __nv_bfloat16* __restrict__ Ahi, const __nv_bfloat16* __restrict__ Alo,
              const __nv_bfloat16* __restrict__ Bhi, const __nv_bfloat16* __restrict__ Blo,
              float* __restrict__ C) {
    constexpr int ST = 40;
    constexpr int BUF = 128 * ST;
    constexpr int CHUNKS = K / 32;
    extern __shared__ __align__(16) char smraw[];
    __nv_bfloat16* s = (__nv_bfloat16*)smraw;     // [2 stages][4 bufs][BUF]

    const int tid  = threadIdx.x;
    const int lane = tid & 31;
    const int wid  = tid >> 5;
    const int wm   = (wid & 1) * 64;
    const int wn   = (wid >> 1) * 32;
    const int m0   = blockIdx.x * 128;
    const int n0   = blockIdx.y * 128;

    float acc[4][4][4];
#pragma unroll
    for (int mt = 0; mt < 4; mt++)
#pragma unroll
        for (int nt = 0; nt < 4; nt++)
#pragma unroll
            for (int j = 0; j < 4; j++) acc[mt][nt][j] = 0.0f;

    const int a_row = wm + (lane & 15);
    const int a_kof = ((lane >> 4) & 1) << 3;
    const int b_row = wn + (lane & 7) + (((lane >> 4) & 1) << 3);
    const int b_kof = ((lane >> 3) & 1) << 3;

    auto issue_chunk = [&](int ch) {
        const int kc0 = ch * 32;
        const int st  = ch & 1;
#pragma unroll
        for (int it = 0; it < 8; it++) {
            int j   = it * 256 + tid;
            int buf = j >> 9;
            int r   = (j >> 2) & 127;
            int c   = j & 3;
            const __nv_bfloat16* gb =
                (buf == 0) ? Ahi : (buf == 1) ? Alo : (buf == 2) ? Bhi : Blo;
            int grow = (buf < 2) ? (m0 + r) : (n0 + r);
            int sz = 16;
            if (buf < 2 && grow >= NN) { grow = NN - 1; sz = 0; }   // zero-fill
            uint32_t dst = smem_u32(s + (st * 4 + buf) * BUF + r * ST + c * 8);
            const void* src = gb + (size_t)grow * K + kc0 + c * 8;
            asm volatile("cp.async.cg.shared.global [%0], [%1], 16, %2;"
                         :: "r"(dst), "l"(src), "r"(sz));
        }
        asm volatile("cp.async.commit_group;" ::: "memory");
    };

    issue_chunk(0);
    if (CHUNKS > 1) issue_chunk(1);

    for (int ch = 0; ch < CHUNKS; ch++) {
        if (ch + 1 < CHUNKS)
            asm volatile("cp.async.wait_group 1;" ::: "memory");
        else
            asm volatile("cp.async.wait_group 0;" ::: "memory");
        __syncthreads();

        const int st = ch & 1;
        uint32_t base0 = smem_u32(s + (st * 4 + 0) * BUF);
        uint32_t base1 = smem_u32(s + (st * 4 + 1) * BUF);
        uint32_t base2 = smem_u32(s + (st * 4 + 2) * BUF);
        uint32_t base3 = smem_u32(s + (st * 4 + 3) * BUF);
#pragma unroll
        for (int ks = 0; ks < 2; ks++) {
            uint32_t ah[4][4], al[4][4], bh[2][4], bl[2][4];
#pragma unroll
            for (int mt = 0; mt < 4; mt++) {
                uint32_t off = ((a_row + mt * 16) * ST + ks * 16 + a_kof) * 2;
                ldmx4(ah[mt], base0 + off);
                ldmx4(al[mt], base1 + off);
            }
#pragma unroll
            for (int p = 0; p < 2; p++) {
                uint32_t off = ((b_row + p * 16) * ST + ks * 16 + b_kof) * 2;
                ldmx4(bh[p], base2 + off);
                ldmx4(bl[p], base3 + off);
            }
#pragma unroll
            for (int mt = 0; mt < 4; mt++)
#pragma unroll
                for (int nt = 0; nt < 4; nt++) {
                    int p = nt >> 1, q = (nt & 1) * 2;
                    mma16816(acc[mt][nt], ah[mt], bh[p][q], bh[p][q + 1]);
                    mma16816(acc[mt][nt], ah[mt], bl[p][q], bl[p][q + 1]);
                    mma16816(acc[mt][nt], al[mt], bh[p][q], bh[p][q + 1]);
                }
        }
        __syncthreads();
        if (ch + 2 < CHUNKS) issue_chunk(ch + 2);
    }

#pragma unroll
    for (int mt = 0; mt < 4; mt++) {
        int row0 = m0 + wm + mt * 16 + (lane >> 2);
        int row1 = row0 + 8;
#pragma unroll
        for (int nt = 0; nt < 4; nt++) {
            int col = n0 + wn + nt * 8 + (lane & 3) * 2;
            if (row0 < NN)
                *(float2*)(C + (size_t)row0 * NT + col) =
                    make_float2(acc[mt][nt][0], acc[mt][nt][1]);
            if (row1 < NN)
                *(float2*)(C + (size_t)row1 * NT + col) =
                    make_float2(acc[mt][nt][2], acc[mt][nt][3]);
        }
    }
}

// ============================ fused CSR gather ============================
template <int C, bool SPLIT>
__global__ __launch_bounds__(256)
void k_gather(const float* __restrict__ h, const float* __restrict__ bias,
              float* __restrict__ outf, __nv_bfloat16* __restrict__ outhi,
              __nv_bfloat16* __restrict__ outlo) {
    constexpr int L = C / 4;
    constexpr int NPB = 256 / L;
    int node = blockIdx.x * NPB + threadIdx.x / L;
    if (node >= NN) return;
    int lane = threadIdx.x % L;

    const float4* h4 = (const float4*)h;
    float dd = g_dinv[node];
    float4 self = h4[(size_t)node * L + lane];
    float ws = dd * dd;
    float4 acc = make_float4(self.x * ws, self.y * ws, self.z * ws, self.w * ws);

    int e   = g_rowptr[node];
    int end = g_rowptr[node + 1];
    for (; e + 1 < end; e += 2) {
        int s0 = __ldg(&g_esrc[e]);
        int s1 = __ldg(&g_esrc[e + 1]);
        float w0 = __ldg(&g_dinv[s0]) * dd;
        float w1 = __ldg(&g_dinv[s1]) * dd;
        float4 v0 = h4[(size_t)s0 * L + lane];
        float4 v1 = h4[(size_t)s1 * L + lane];
        acc.x = fmaf(v0.x, w0, fmaf(v1.x, w1, acc.x));
        acc.y = fmaf(v0.y, w0, fmaf(v1.y, w1, acc.y));
        acc.z = fmaf(v0.z, w0, fmaf(v1.z, w1, acc.z));
        acc.w = fmaf(v0.w, w0, fmaf(v1.w, w1, acc.w));
    }
    if (e < end) {
        int s0 = __ldg(&g_esrc[e]);
        float w0 = __ldg(&g_dinv[s0]) * dd;
        float4 v0 = h4[(size_t)s0 * L + lane];
        acc.x = fmaf(v0.x, w0, acc.x);
        acc.y = fmaf(v0.y, w0, acc.y);
        acc.z = fmaf(v0.z, w0, acc.z);
        acc.w = fmaf(v0.w, w0, acc.w);
    }

    float4 b = ((const float4*)bias)[lane];
    acc.x += b.x; acc.y += b.y; acc.z += b.z; acc.w += b.w;

    if (SPLIT) {
        acc.x = fmaxf(acc.x, 0.f); acc.y = fmaxf(acc.y, 0.f);
        acc.z = fmaxf(acc.z, 0.f); acc.w = fmaxf(acc.w, 0.f);
        __nv_bfloat16 hx = __float2bfloat16(acc.x), hy = __float2bfloat16(acc.y);
        __nv_bfloat16 hz = __float2bfloat16(acc.z), hw = __float2bfloat16(acc.w);
        size_t p2 = ((size_t)node * L + lane) * 2;
        ((__nv_bfloat162*)outhi)[p2]     = __nv_bfloat162{hx, hy};
        ((__nv_bfloat162*)outhi)[p2 + 1] = __nv_bfloat162{hz, hw};
        ((__nv_bfloat162*)outlo)[p2] = __nv_bfloat162{
            __float2bfloat16(acc.x - __bfloat162float(hx)),
            __float2bfloat16(acc.y - __bfloat162float(hy))};
        ((__nv_bfloat162*)outlo)[p2 + 1] = __nv_bfloat162{
            __float2bfloat16(acc.z - __bfloat162float(hz)),
            __float2bfloat16(acc.w - __bfloat162float(hw))};
    } else {
        ((float4*)outf)[(size_t)node * L + lane] = acc;
    }
}

// ============================ launch ============================
extern "C" void kernel_launch(void* const* d_in, const int* in_sizes, int n_in,
                              void* d_out, int out_size) {
    const float* x  = (const float*)d_in[0];
    const void*  ei = d_in[1];
    const float* W1 = (const float*)d_in[2];
    const float* b1 = (const float*)d_in[3];
    const float* W2 = (const float*)d_in[4];
    const float* b2 = (const float*)d_in[5];
    float*       out = (float*)d_out;

    float *h1, *h2;
    __nv_bfloat16 *aghi, *aglo, *w1hi, *w1lo, *w2hi, *w2lo;
    cudaGetSymbolAddress((void**)&h1, g_h1);
    cudaGetSymbolAddress((void**)&h2, g_h2);
    cudaGetSymbolAddress((void**)&aghi, g_aghi);
    cudaGetSymbolAddress((void**)&aglo, g_aglo);
    cudaGetSymbolAddress((void**)&w1hi, g_w1hi);
    cudaGetSymbolAddress((void**)&w1lo, g_w1lo);
    cudaGetSymbolAddress((void**)&w2hi, g_w2hi);
    cudaGetSymbolAddress((void**)&w2lo, g_w2lo);

    // one-time host-object setup (no device memory involved)
    static cudaStream_t s2 = nullptr;
    static cudaEvent_t ev_fork = nullptr, ev_join = nullptr;
    if (!s2) {
        cudaStreamCreateWithFlags(&s2, cudaStreamNonBlocking);
        cudaEventCreateWithFlags(&ev_fork, cudaEventDisableTiming);
        cudaEventCreateWithFlags(&ev_join, cudaEventDisableTiming);
        constexpr int SM2 = 2 * 4 * 128 * 40 * 2;   // 81920 B
        cudaFuncSetAttribute(k_mma_bf<HID, OUTC>,
                             cudaFuncAttributeMaxDynamicSharedMemorySize, SM2);
    }
    constexpr int SM2 = 2 * 4 * 128 * 40 * 2;       // 81920 B

    const int NB = (NN + 127) / 128;   // 391

    // ---- fork ----
    cudaEventRecord(ev_fork, 0);
    cudaStreamWaitEvent(s2, ev_fork, 0);

    // side stream: splitT2 + CSR build (hidden under splitT1 + GEMM1)
    k_splitT<<<(HID * OUTC + 255) / 256, 256, 0, s2>>>(W2, w2hi, w2lo, HID, OUTC);
    k_prep  <<<(NN + 255) / 256, 256, 0, s2>>>();
    k_count <<<(NE + 255) / 256, 256, 0, s2>>>(ei);
    k_scan1 <<<NSCAN_BLK, 256, 0, s2>>>();
    k_scan2 <<<1, 256, 0, s2>>>();
    k_scan3 <<<NSCAN_BLK, 256, 0, s2>>>();
    k_fill  <<<(NE + 255) / 256, 256, 0, s2>>>(ei);
    cudaEventRecord(ev_join, s2);

    // main stream: splitT1 + GEMM1 (fused x fp32->bf16 split, register prefetch)
    k_splitT<<<(IN_CH * HID + 255) / 256, 256>>>(W1, w1hi, w1lo, IN_CH, HID);
    dim3 g1(NB, HID / 128);
    k_mma_f32<IN_CH, HID><<<g1, 256>>>(x, w1hi, w1lo, h1);

    // ---- join, then serial tail ----
    cudaStreamWaitEvent(0, ev_join, 0);
    k_gather<HID, true><<<(NN + 3) / 4, 256>>>(h1, b1, nullptr, aghi, aglo);

    dim3 g2(NB, OUTC / 128);
    k_mma_bf<HID, OUTC><<<g2, 256, SM2>>>(aghi, aglo, w2hi, w2lo, h2);
    k_gather<OUTC, false><<<(NN + 7) / 8, 256>>>(h2, b2, out, nullptr, nullptr);
}